// round 12
// baseline (speedup 1.0000x reference)
#include <cuda_runtime.h>
#include <cstdint>

// LSTM(B=8192, T=1024, H=10, in=1) -> final cell state c_T -> Linear(10,1).
//
// R11: A/B test of MIO-throughput vs instruction-count as the binding
// constraint. Same decomposition as R8 (champion, 240.1us): 10 lanes/batch,
// 3 batches/warp, 2731 single-warp blocks. Change: h-table stored
// NON-duplicated (40B/group) and gates accumulated K-PAIRED, cutting smem
// ops per warp-step from 6 (1 STS.64 + 5 LDS.128) to 4 (1 STS.32 +
// 2 LDS.128 + 1 LDS.64), at the cost of ~3 extra fma-pipe instructions.
// f32 tanh restored (R10's f16 pack regressed speed AND precision).
//
// Math: tanh.approx.f32; sigma(x)=0.5+0.5*tanh(x/2) folded into pre-scaled
// weights; state h'=2h folded into W_hh; x and bias folded via (x,1) pair.

#define B_TOT 8192
#define T_LEN 1024
#define HID   10
#define GPW   3
#define GSTRIDE 12              // floats per group region (48B)

typedef unsigned long long ull;

__device__ __forceinline__ ull pack2(float x, float y) {
    ull r;
    asm("mov.b64 %0, {%1, %2};" : "=l"(r) : "f"(x), "f"(y));
    return r;
}
__device__ __forceinline__ void unpack2(ull v, float& x, float& y) {
    asm("mov.b64 {%0, %1}, %2;" : "=f"(x), "=f"(y) : "l"(v));
}
__device__ __forceinline__ ull ffma2(ull a, ull b, ull c) {
    ull d;
    asm("fma.rn.f32x2 %0, %1, %2, %3;" : "=l"(d) : "l"(a), "l"(b), "l"(c));
    return d;
}
__device__ __forceinline__ ull fmul2(ull a, ull b) {
    ull d;
    asm("mul.rn.f32x2 %0, %1, %2;" : "=l"(d) : "l"(a), "l"(b));
    return d;
}
__device__ __forceinline__ float ftanh(float x) {
    float r;
    asm("tanh.approx.f32 %0, %1;" : "=f"(r) : "f"(x));
    return r;
}
__device__ __forceinline__ void lds_v2b64(uint32_t addr, ull& a, ull& b) {
    asm volatile("ld.shared.v2.b64 {%0, %1}, [%2];" : "=l"(a), "=l"(b) : "r"(addr));
}
__device__ __forceinline__ ull lds_b64(uint32_t addr) {
    ull a;
    asm volatile("ld.shared.b64 %0, [%1];" : "=l"(a) : "r"(addr));
    return a;
}
__device__ __forceinline__ void sts_f32(uint32_t addr, float v) {
    asm volatile("st.shared.f32 [%0], %1;" :: "r"(addr), "f"(v) : "memory");
}
__device__ __forceinline__ uint32_t smem_u32(const void* p) {
    uint32_t a;
    asm("{ .reg .u64 t; cvta.to.shared.u64 t, %1; cvt.u32.u64 %0, t; }"
        : "=r"(a) : "l"(p));
    return a;
}

__global__ __launch_bounds__(32)
void lstm_lin_kernel(const float* __restrict__ x,       // [B, T, 1]
                     const float* __restrict__ W_ih,    // [4H, 1]
                     const float* __restrict__ W_hh,    // [4H, H]
                     const float* __restrict__ b_ih,    // [4H]
                     const float* __restrict__ b_hh,    // [4H]
                     const float* __restrict__ W_lin,   // [1, H]
                     const float* __restrict__ b_lin,   // [1]
                     float* __restrict__ out)           // [B, 1]
{
    // [parity][group][12 floats]: non-duplicated h at float index r.
    // Group bases at banks {0,12,24}: LDS.128/64 group-broadcast reads are
    // conflict-free; STS.32 worst case 2-way on 2 lanes.
    __shared__ float hbuf[2][GPW][GSTRIDE];

    const int wlane = threadIdx.x;          // single-warp block
    const int group = wlane / HID;          // 0..2 active; 3 => lanes 30,31
    const int r     = wlane - group * HID;  // unit 0..9
    const int base  = group * HID;
    const bool active = (group < GPW);
    const int sgrp   = active ? group : 0;

    const int gbatch = blockIdx.x * GPW + group;
    const bool valid = active && (gbatch < B_TOT);
    const int b = valid ? gbatch : 0;

    // ---- per-lane weights, K-paired & pre-scaled ----
    // gate g in {i,f,g,o}: sg = 0.5 (sigmoid) or 1.0 (tanh gate).
    // w2[g][j] = sg*0.5*(W_hh[row][2j], W_hh[row][2j+1])  (0.5 = h'=2h fold)
    // wxb[g]   = (sg*W_ih[row], sg*(b_ih[row]+b_hh[row])) against xp=(x,1).
    ull w2[4][5], wxb[4];
#pragma unroll
    for (int g = 0; g < 4; g++) {
        const float sg = (g == 2) ? 1.0f : 0.5f;
        const int row = g * HID + r;
#pragma unroll
        for (int j = 0; j < 5; j++)
            w2[g][j] = pack2(W_hh[row * HID + 2 * j]     * sg * 0.5f,
                             W_hh[row * HID + 2 * j + 1] * sg * 0.5f);
        wxb[g] = pack2(W_ih[row] * sg, (b_ih[row] + b_hh[row]) * sg);
    }

    float c = 0.0f;

    const uint32_t smem0 = smem_u32(&hbuf[0][0][0]);
    const uint32_t grp_base0 = smem0 + (uint32_t)sgrp * (GSTRIDE * 4);
    const uint32_t grp_base1 = grp_base0 + GPW * GSTRIDE * 4;    // parity-1
    const uint32_t slot0 = grp_base0 + r * 4;
    const uint32_t slot1 = grp_base1 + r * 4;

    if (active) sts_f32(slot0, 0.0f);
    __syncwarp();

    const float4* __restrict__ xrow =
        reinterpret_cast<const float4*>(x + (size_t)b * T_LEN);

    for (int t4 = 0; t4 < T_LEN / 4; t4++) {
        const float4 xq = __ldg(&xrow[t4]);
        ull xps[4];
        xps[0] = pack2(xq.x, 1.0f);
        xps[1] = pack2(xq.y, 1.0f);
        xps[2] = pack2(xq.z, 1.0f);
        xps[3] = pack2(xq.w, 1.0f);

#pragma unroll
        for (int jt = 0; jt < 4; jt++) {
            const uint32_t rd = (jt & 1) ? grp_base1 : grp_base0;
            const uint32_t wr = (jt & 1) ? slot0 : slot1;

            // 2x LDS.128 + 1x LDS.64 -> 5 h'-pairs (h2j, h2j+1), reg-aligned
            ull hp[5];
            lds_v2b64(rd +  0, hp[0], hp[1]);
            lds_v2b64(rd + 16, hp[2], hp[3]);
            hp[4] = lds_b64(rd + 32);

            const ull xp = xps[jt];

            // k-paired gate accumulation: 6 f32x2 ops per gate
            float t[4];
#pragma unroll
            for (int g = 0; g < 4; g++) {
                ull acc = ffma2(w2[g][0], hp[0], fmul2(wxb[g], xp));
                acc = ffma2(w2[g][1], hp[1], acc);
                acc = ffma2(w2[g][2], hp[2], acc);
                acc = ffma2(w2[g][3], hp[3], acc);
                acc = ffma2(w2[g][4], hp[4], acc);
                float lo, hi;
                unpack2(acc, lo, hi);      // register-pair alias: ~free
                t[g] = ftanh(lo + hi);
            }

            // c = sigma_f*c + sigma_i*tanh_g ; sigma = 0.5 + 0.5*t
            const float sf = fmaf(0.5f, t[1], 0.5f);
            const float si = fmaf(0.5f, t[0], 0.5f);
            c = fmaf(sf, c, si * t[2]);

            // h' = 2h = (1 + tanh_o) * tanh(c); store scalar (non-dup)
            const float tc = ftanh(c);
            const float hn = fmaf(t[3], tc, tc);
            if (active) sts_f32(wr, hn);

            asm volatile("" ::: "memory");  // pin STS(t) before LDS(t+1)
        }
    }

    // ---- epilogue: out[b] = sum_u c[u] * W_lin[u] + b_lin ----
    float part = c * W_lin[r];
    float sum = part;
#pragma unroll
    for (int j = 1; j < HID; j++)
        sum += __shfl_sync(0xffffffffu, part, base + j);

    if (valid && r == 0) {
        out[gbatch] = sum + b_lin[0];
    }
}

extern "C" void kernel_launch(void* const* d_in, const int* in_sizes, int n_in,
                              void* d_out, int out_size) {
    const float* x     = (const float*)d_in[0];
    const float* W_ih  = (const float*)d_in[1];
    const float* W_hh  = (const float*)d_in[2];
    const float* b_ih  = (const float*)d_in[3];
    const float* b_hh  = (const float*)d_in[4];
    const float* W_lin = (const float*)d_in[5];
    const float* b_lin = (const float*)d_in[6];
    float* out = (float*)d_out;

    const int blocks = (B_TOT + GPW - 1) / GPW;   // 2731 single-warp blocks
    lstm_lin_kernel<<<blocks, 32>>>(
        x, W_ih, W_hh, b_ih, b_hh, W_lin, b_lin, out);
}

// round 14
// speedup vs baseline: 1.0870x; 1.0870x over previous
#include <cuda_runtime.h>
#include <cstdint>

// LSTM(B=8192, T=1024, H=10, in=1) -> final cell state c_T -> Linear(10,1).
//
// R13 = R12 banking fix, corrected for alignment. R12's 88B stride broke
// 16B alignment of ld.shared.v2.b64 (group-1 base at 88B) -> misaligned
// address trap. New stride 80B (20 floats):
//   * every group/plane base 16B-aligned (80, 160, 240... all %16==0)
//   * group bases at banks 0/20/8 (plane0) and 28/16/4 (plane1):
//       - all 5 group-broadcast LDS.128/64 reads conflict-free (verified
//         per-offset: bank quads disjoint across the 3 groups)
//       - dup-pair STS.64 drops from R8's uniform 3-way conflict to max
//         2-way -> per-step MIO wavefronts 8 -> 7.
// Math identical to champion R8 (~37 instr/step): duplicated-h table,
// gate-PAIR f32x2 accumulation, f32 tanh.approx, sigma folded into
// pre-scaled weights, h' = 2h, no per-step sync.

#define B_TOT 8192
#define T_LEN 1024
#define HID   10
#define GPW   3
#define GSTRIDE 20              // floats per group region (80B, 16B-aligned)

typedef unsigned long long ull;

__device__ __forceinline__ ull pack2(float x, float y) {
    ull r;
    asm("mov.b64 %0, {%1, %2};" : "=l"(r) : "f"(x), "f"(y));
    return r;
}
__device__ __forceinline__ ull ffma2(ull a, ull b, ull c) {
    ull d;
    asm("fma.rn.f32x2 %0, %1, %2, %3;" : "=l"(d) : "l"(a), "l"(b), "l"(c));
    return d;
}
__device__ __forceinline__ float ftanh(float x) {
    float r;
    asm("tanh.approx.f32 %0, %1;" : "=f"(r) : "f"(x));
    return r;
}
__device__ __forceinline__ void lds_v2b64(uint32_t addr, ull& a, ull& b) {
    asm volatile("ld.shared.v2.b64 {%0, %1}, [%2];" : "=l"(a), "=l"(b) : "r"(addr));
}
__device__ __forceinline__ void sts_dup(uint32_t addr, float v) {
    asm volatile("st.shared.v2.f32 [%0], {%1, %1};" :: "r"(addr), "f"(v) : "memory");
}
__device__ __forceinline__ uint32_t smem_u32(const void* p) {
    uint32_t a;
    asm("{ .reg .u64 t; cvta.to.shared.u64 t, %1; cvt.u32.u64 %0, t; }"
        : "=r"(a) : "l"(p));
    return a;
}

__global__ __launch_bounds__(32)
void lstm_lin_kernel(const float* __restrict__ x,       // [B, T, 1]
                     const float* __restrict__ W_ih,    // [4H, 1]
                     const float* __restrict__ W_hh,    // [4H, H]
                     const float* __restrict__ b_ih,    // [4H]
                     const float* __restrict__ b_hh,    // [4H]
                     const float* __restrict__ W_lin,   // [1, H]
                     const float* __restrict__ b_lin,   // [1]
                     float* __restrict__ out)           // [B, 1]
{
    // [parity][group][20 floats]; dup h-pairs at float offsets 2r, 2r+1.
    __shared__ float hbuf[2][GPW][GSTRIDE];

    const int wlane = threadIdx.x;          // single-warp block
    const int group = wlane / HID;          // 0..2 active; 3 => lanes 30,31
    const int r     = wlane - group * HID;  // unit 0..9
    const int base  = group * HID;
    const bool active = (group < GPW);
    const int sgrp   = active ? group : 0;

    const int gbatch = blockIdx.x * GPW + group;
    const bool valid = active && (gbatch < B_TOT);
    const int b = valid ? gbatch : 0;

    // ---- per-lane weights, GATE-paired & pre-scaled (identical to R8) ----
    ull wif[HID], wgo[HID];
#pragma unroll
    for (int k = 0; k < HID; k++) {
        wif[k] = pack2(W_hh[(0 * HID + r) * HID + k] * 0.25f,
                       W_hh[(1 * HID + r) * HID + k] * 0.25f);
        wgo[k] = pack2(W_hh[(2 * HID + r) * HID + k] * 0.50f,
                       W_hh[(3 * HID + r) * HID + k] * 0.25f);
    }
    const ull wxif = pack2(W_ih[0 * HID + r] * 0.5f, W_ih[1 * HID + r] * 0.5f);
    const ull wxgo = pack2(W_ih[2 * HID + r] * 1.0f, W_ih[3 * HID + r] * 0.5f);
    const ull bif  = pack2((b_ih[0 * HID + r] + b_hh[0 * HID + r]) * 0.5f,
                           (b_ih[1 * HID + r] + b_hh[1 * HID + r]) * 0.5f);
    const ull bgo  = pack2((b_ih[2 * HID + r] + b_hh[2 * HID + r]) * 1.0f,
                           (b_ih[3 * HID + r] + b_hh[3 * HID + r]) * 0.5f);

    float c = 0.0f;

    const uint32_t smem0 = smem_u32(&hbuf[0][0][0]);
    const uint32_t grp_base0 = smem0 + (uint32_t)sgrp * (GSTRIDE * 4);
    const uint32_t grp_base1 = grp_base0 + GPW * GSTRIDE * 4;   // parity-1
    const uint32_t slot0 = grp_base0 + r * 8;
    const uint32_t slot1 = grp_base1 + r * 8;

    if (active) sts_dup(slot0, 0.0f);
    __syncwarp();

    const float4* __restrict__ xrow =
        reinterpret_cast<const float4*>(x + (size_t)b * T_LEN);

    for (int t4 = 0; t4 < T_LEN / 4; t4++) {
        const float4 xq = __ldg(&xrow[t4]);
        ull xx[4];
        xx[0] = pack2(xq.x, xq.x);
        xx[1] = pack2(xq.y, xq.y);
        xx[2] = pack2(xq.z, xq.z);
        xx[3] = pack2(xq.w, xq.w);

#pragma unroll
        for (int jt = 0; jt < 4; jt++) {
            const uint32_t rd = (jt & 1) ? grp_base1 : grp_base0;
            const uint32_t wr = (jt & 1) ? slot0 : slot1;

            // 5 loads -> 10 duplicated h'-pairs (conflict-free broadcast)
            ull hd[HID];
            lds_v2b64(rd +  0, hd[0], hd[1]);
            lds_v2b64(rd + 16, hd[2], hd[3]);
            lds_v2b64(rd + 32, hd[4], hd[5]);
            lds_v2b64(rd + 48, hd[6], hd[7]);
            lds_v2b64(rd + 64, hd[8], hd[9]);

            ull acc_if = ffma2(xx[jt], wxif, bif);
            ull acc_go = ffma2(xx[jt], wxgo, bgo);
#pragma unroll
            for (int k = 0; k < HID; k++) {
                acc_if = ffma2(wif[k], hd[k], acc_if);
                acc_go = ffma2(wgo[k], hd[k], acc_go);
            }

            // halves alias the 64-bit accumulators (no forced MOVs)
            const float2 gif = *reinterpret_cast<const float2*>(&acc_if);
            const float2 ggo = *reinterpret_cast<const float2*>(&acc_go);
            const float ti = ftanh(gif.x);
            const float tf = ftanh(gif.y);
            const float tg = ftanh(ggo.x);
            const float to = ftanh(ggo.y);

            // c = sigma_f*c + sigma_i*tanh_g ; sigma = 0.5 + 0.5*t
            const float sf = fmaf(0.5f, tf, 0.5f);
            const float si = fmaf(0.5f, ti, 0.5f);
            c = fmaf(sf, c, si * tg);

            // h' = 2h = (1 + tanh_o) * tanh(c); store duplicated
            const float tc = ftanh(c);
            const float hn = fmaf(to, tc, tc);
            if (active) sts_dup(wr, hn);

            asm volatile("" ::: "memory");   // pin STS(t) before LDS(t+1)
        }
    }

    // ---- epilogue: out[b] = sum_u c[u] * W_lin[u] + b_lin ----
    float part = c * W_lin[r];
    float sum = part;
#pragma unroll
    for (int j = 1; j < HID; j++)
        sum += __shfl_sync(0xffffffffu, part, base + j);

    if (valid && r == 0) {
        out[gbatch] = sum + b_lin[0];
    }
}

extern "C" void kernel_launch(void* const* d_in, const int* in_sizes, int n_in,
                              void* d_out, int out_size) {
    const float* x     = (const float*)d_in[0];
    const float* W_ih  = (const float*)d_in[1];
    const float* W_hh  = (const float*)d_in[2];
    const float* b_ih  = (const float*)d_in[3];
    const float* b_hh  = (const float*)d_in[4];
    const float* W_lin = (const float*)d_in[5];
    const float* b_lin = (const float*)d_in[6];
    float* out = (float*)d_out;

    const int blocks = (B_TOT + GPW - 1) / GPW;   // 2731 single-warp blocks
    lstm_lin_kernel<<<blocks, 32>>>(
        x, W_ih, W_hh, b_ih, b_hh, W_lin, b_lin, out);
}